// round 10
// baseline (speedup 1.0000x reference)
#include <cuda_runtime.h>
#include <cuda_bf16.h>
#include <mma.h>
#include <cstdint>

using namespace nvcuda;

#define NB 64
#define NN 1024
#define ND 128
#define THRESH 0.15f      // 0.5 - MARGIN(0.35)
#define TM 128
#define TN 128
#define LDSE 136          // smem leading dim in bf16 elems (272B rows)
#define ROWB (LDSE * 2)
#define TILE_BYTES (TM * ROWB)        // 34816
#define SMEM_DYN (3 * TILE_BYTES)     // A + 2x B = 104448 (occ 2)
#define GEMM_CTAS (8 * NB)            // 512

// Scratch (device globals; no allocation allowed)
__device__ __nv_bfloat16 g_P[(size_t)NB * NN * ND];
__device__ __nv_bfloat16 g_Q[(size_t)NB * NN * ND];
__device__ unsigned short g_dest[NB * NN];
__device__ int   g_npos[NB];
__device__ int   g_nneg[NB];
__device__ float g_bsum[NB];
__device__ unsigned int g_done;
__device__ unsigned int g_ready[NB];   // per-batch scan-done generation counter
__device__ unsigned int g_gen;         // replay generation (monotonic)

__device__ __forceinline__ uint32_t smem_u32(const void* p) {
    uint32_t a;
    asm("{ .reg .u64 t; cvta.to.shared.u64 t, %1; cvt.u32.u64 %0, t; }" : "=r"(a) : "l"(p));
    return a;
}
__device__ __forceinline__ void cp16(uint32_t dst, const void* src) {
    asm volatile("cp.async.cg.shared.global [%0], [%1], 16;" :: "r"(dst), "l"(src));
}
#define CP_COMMIT() asm volatile("cp.async.commit_group;" ::: "memory")
#define CP_WAIT(n)  asm volatile("cp.async.wait_group %0;" :: "n"(n) : "memory")

// ---------------------------------------------------------------------------
// Kernel A: scan (x==0 CTA per batch) + normalize/scatter (x=1..128), fused.
// grid = (129, 64), 256 threads. Normalize CTAs overlap their embedding
// loads with the scan, then acquire-spin on the per-batch ready flag.
// ---------------------------------------------------------------------------
__global__ void __launch_bounds__(256)
normalize_fused_kernel(const float* __restrict__ emb,
                       const int*   __restrict__ labels)
{
    const int b   = blockIdx.y;
    const int tid = threadIdx.x;
    const int warp = tid >> 5, lane = tid & 31;

    if (blockIdx.x == 0) {
        // ---------------- scan CTA for batch b ----------------
        __shared__ int s_wtot[8];

        int4 l4 = reinterpret_cast<const int4*>(labels + b * NN)[tid];
        int p0 = (l4.x == 1), p1 = (l4.y == 1), p2 = (l4.z == 1), p3 = (l4.w == 1);
        int tsum = p0 + p1 + p2 + p3;

        int incl = tsum;
#pragma unroll
        for (int o = 1; o < 32; o <<= 1) {
            int v = __shfl_up_sync(0xFFFFFFFFu, incl, o);
            if (lane >= o) incl += v;
        }
        if (lane == 31) s_wtot[warp] = incl;
        __syncthreads();
        if (tid < 8) {
            int v = s_wtot[tid];
#pragma unroll
            for (int o = 1; o < 8; o <<= 1) {
                int u = __shfl_up_sync(0x000000FFu, v, o);
                if (lane >= o) v += u;
            }
            s_wtot[tid] = v;
        }
        __syncthreads();

        int run = (warp > 0 ? s_wtot[warp - 1] : 0) + incl - tsum;
        int base4 = tid * 4;
        int pp[4] = {p0, p1, p2, p3};
#pragma unroll
        for (int j = 0; j < 4; j++) {
            int idx = base4 + j;
            int rank = pp[j] ? run : (idx - run);
            g_dest[b * NN + idx] = (unsigned short)(rank | (pp[j] << 15));
            run += pp[j];
        }

        const int npos = s_wtot[7];
        const int nneg = NN - npos;
        if (tid == 0) {
            g_npos[b] = npos; g_nneg[b] = nneg; g_bsum[b] = 0.0f;
            if (b == 0) g_done = 0u;
        }

        // zero-pad tails to 128-row granularity
        const uint4 z4 = make_uint4(0u, 0u, 0u, 0u);
        int pad_pos = min(NN, ((npos + TM - 1) / TM) * TM);
        int pad_neg = min(NN, ((nneg + TN - 1) / TN) * TN);
        int nzp = (pad_pos - npos) * 16;
        for (int i = tid; i < nzp; i += 256) {
            int r = npos + (i >> 4), c = i & 15;
            reinterpret_cast<uint4*>(g_P + ((size_t)b * NN + r) * ND)[c] = z4;
        }
        int nzn = (pad_neg - nneg) * 16;
        for (int i = tid; i < nzn; i += 256) {
            int r = nneg + (i >> 4), c = i & 15;
            reinterpret_cast<uint4*>(g_Q + ((size_t)b * NN + r) * ND)[c] = z4;
        }

        // release: publish scan results, bump per-batch generation
        __syncthreads();
        if (tid == 0) {
            __threadfence();
            atomicAdd(&g_ready[b], 1u);
            if (b == 0) atomicAdd(&g_gen, 1u);   // one global gen bump per replay
        }
        return;
    }

    // ---------------- normalize CTA: rows (x-1)*8 .. +7 ----------------
    const int r = (blockIdx.x - 1) * 8 + warp;

    // scan-independent work first: load + norm (float4 per lane)
    const float4 f4 =
        reinterpret_cast<const float4*>(emb + ((size_t)b * NN + r) * ND)[lane];
    float ss = f4.x * f4.x + f4.y * f4.y + f4.z * f4.z + f4.w * f4.w;
#pragma unroll
    for (int o = 16; o > 0; o >>= 1) ss += __shfl_xor_sync(0xFFFFFFFFu, ss, o);
    float inv = 1.0f / fmaxf(sqrtf(ss), 1e-12f);

    // acquire-spin: wait until this replay's scan for batch b has published.
    // g_ready[b] counts scans completed; it reaches g_gen's current value
    // exactly when batch b's scan of THIS replay is done (both monotonic).
    if (tid == 0) {
        unsigned target = *(volatile unsigned*)&g_gen;   // >= this replay's gen
        while (*(volatile unsigned*)&g_ready[b] < target) { }
        __threadfence();
    }
    __syncthreads();

    unsigned short d = g_dest[b * NN + r];
    int rank  = d & 0x7FFF;
    int ispos = d >> 15;
    __nv_bfloat16* dst = (ispos ? g_P : g_Q) + ((size_t)b * NN + rank) * ND;

    __nv_bfloat162 h0 = __floats2bfloat162_rn(f4.x * inv, f4.y * inv);
    __nv_bfloat162 h1 = __floats2bfloat162_rn(f4.z * inv, f4.w * inv);
    uint2 pk = make_uint2(*reinterpret_cast<uint32_t*>(&h0),
                          *reinterpret_cast<uint32_t*>(&h1));
    reinterpret_cast<uint2*>(dst)[lane] = pk;
}

// ---------------------------------------------------------------------------
// Kernel B: A-resident streaming GEMM (R7 winner, verbatim).
// CTA = (ti, b); A loaded once, B tiles double-buffered. grid (8,64), occ 2.
// ---------------------------------------------------------------------------
__global__ void __launch_bounds__(256, 2)
hinge_gemm_kernel(float* __restrict__ out)
{
    extern __shared__ __align__(16) char smem[];
    const uint32_t smem_base = smem_u32(smem);
    const int tid  = threadIdx.x;
    const int warp = tid >> 5;
    const int lane = tid & 31;

    const int ti = blockIdx.x;
    const int b  = blockIdx.y;
    const int npos = g_npos[b];
    const int nneg = g_nneg[b];
    const int njt  = (nneg + TN - 1) / TN;
    const bool active = (ti * TM < npos) && (njt > 0);

    if (active) {
        const char* P  = (const char*)(g_P + ((size_t)b * NN + ti * TM) * ND);
        const char* Qb = (const char*)(g_Q + (size_t)b * NN * ND);
        const uint32_t sAa  = smem_base;
        const uint32_t sB0a = smem_base + TILE_BYTES;

        for (int t = tid; t < TM * 16; t += 256) {
            int r = t >> 4, c = t & 15;
            cp16(sAa + r * ROWB + c * 16, P + (size_t)r * ND * 2 + c * 16);
            cp16(sB0a + r * ROWB + c * 16, Qb + (size_t)r * ND * 2 + c * 16);
        }
        CP_COMMIT();

        const __nv_bfloat16* sA = (const __nv_bfloat16*)(smem);
        const int wrow = warp >> 1;
        const int wcol = warp & 1;

        float s = 0.0f;

        for (int tj = 0; tj < njt; tj++) {
            const int cbuf = tj & 1;
            if (tj + 1 < njt) {
                const char* Qn = Qb + (size_t)(tj + 1) * TN * ND * 2;
                uint32_t sBn = smem_base + TILE_BYTES * (1 + ((tj + 1) & 1));
                for (int t = tid; t < TN * 16; t += 256) {
                    int r = t >> 4, c = t & 15;
                    cp16(sBn + r * ROWB + c * 16, Qn + (size_t)r * ND * 2 + c * 16);
                }
                CP_COMMIT();
                CP_WAIT(1);
            } else {
                CP_WAIT(0);
            }
            __syncthreads();

            const __nv_bfloat16* sB =
                (const __nv_bfloat16*)(smem + TILE_BYTES * (1 + cbuf));

            wmma::fragment<wmma::accumulator, 16, 16, 16, float> acc[2][4];
#pragma unroll
            for (int i = 0; i < 2; i++)
#pragma unroll
                for (int j = 0; j < 4; j++) wmma::fill_fragment(acc[i][j], 0.0f);

#pragma unroll
            for (int k = 0; k < ND; k += 16) {
                wmma::fragment<wmma::matrix_a, 16, 16, 16, __nv_bfloat16, wmma::row_major> a[2];
                wmma::fragment<wmma::matrix_b, 16, 16, 16, __nv_bfloat16, wmma::col_major> bb[4];
#pragma unroll
                for (int i = 0; i < 2; i++)
                    wmma::load_matrix_sync(a[i], sA + (wrow * 32 + i * 16) * LDSE + k, LDSE);
#pragma unroll
                for (int j = 0; j < 4; j++)
                    wmma::load_matrix_sync(bb[j], sB + (wcol * 64 + j * 16) * LDSE + k, LDSE);
#pragma unroll
                for (int i = 0; i < 2; i++)
#pragma unroll
                    for (int j = 0; j < 4; j++)
                        wmma::mma_sync(acc[i][j], a[i], bb[j], acc[i][j]);
            }

#pragma unroll
            for (int i = 0; i < 2; i++)
#pragma unroll
                for (int j = 0; j < 4; j++)
#pragma unroll
                    for (int e = 0; e < acc[i][j].num_elements; e++)
                        s += fmaxf(acc[i][j].x[e] - THRESH, 0.0f);

            __syncthreads();
        }

#pragma unroll
        for (int o = 16; o > 0; o >>= 1) s += __shfl_xor_sync(0xFFFFFFFFu, s, o);
        __shared__ float s_w[8];
        if (lane == 0) s_w[warp] = s;
        __syncthreads();
        if (tid == 0) {
            float ts = 0.0f;
#pragma unroll
            for (int i = 0; i < 8; i++) ts += s_w[i];
            atomicAdd(&g_bsum[b], ts);
        }
    }

    // completion ticket; last CTA computes the final scalar
    __shared__ unsigned int s_rank;
    if (tid == 0) {
        __threadfence();
        s_rank = atomicAdd(&g_done, 1u);
    }
    __syncthreads();
    if (s_rank == GEMM_CTAS - 1 && tid == 0) {
        __threadfence();
        float L = 0.0f, C = 0.0f;
        for (int i = 0; i < NB; i++) {
            int np = g_npos[i], nn = g_nneg[i];
            if (np > 0 && nn > 0) {
                L += g_bsum[i] / (float)nn;
                C += (float)np;
            }
        }
        out[0] = L / fmaxf(C, 1.0f);
    }
}

// ---------------------------------------------------------------------------
extern "C" void kernel_launch(void* const* d_in, const int* in_sizes, int n_in,
                              void* d_out, int out_size)
{
    const float* emb    = (const float*)d_in[0];
    const int*   labels = (const int*)d_in[1];
    float*       out    = (float*)d_out;

    cudaFuncSetAttribute(hinge_gemm_kernel,
                         cudaFuncAttributeMaxDynamicSharedMemorySize, SMEM_DYN);

    dim3 gridA(NN / 8 + 1, NB);   // (129, 64): x==0 scans, x=1..128 normalize
    normalize_fused_kernel<<<gridA, 256>>>(emb, labels);

    dim3 gridB(8, NB);            // (ti, b) = 512 CTAs
    hinge_gemm_kernel<<<gridB, 256, SMEM_DYN>>>(out);
}

// round 11
// speedup vs baseline: 1.3877x; 1.3877x over previous
#include <cuda_runtime.h>
#include <cuda_bf16.h>
#include <mma.h>
#include <cstdint>

using namespace nvcuda;

#define NB 64
#define NN 1024
#define ND 128
#define THRESH 0.15f      // 0.5 - MARGIN(0.35)
#define TM 128
#define TN 128
#define LDSE 136          // smem leading dim in bf16 elems (272B rows)
#define ROWB (LDSE * 2)
#define TILE_BYTES (TM * ROWB)        // 34816
#define SMEM_DYN (3 * TILE_BYTES)     // A + 2x B = 104448 (occ 2)
#define GEMM_CTAS (8 * NB)            // 512

// Scratch (device globals; no allocation allowed)
__device__ __nv_bfloat16 g_P[(size_t)NB * NN * ND];
__device__ __nv_bfloat16 g_Q[(size_t)NB * NN * ND];
__device__ unsigned short g_dest[NB * NN];
__device__ int   g_npos[NB];
__device__ int   g_nneg[NB];
__device__ float g_bsum[NB];
__device__ unsigned int g_done;

__device__ __forceinline__ uint32_t smem_u32(const void* p) {
    uint32_t a;
    asm("{ .reg .u64 t; cvta.to.shared.u64 t, %1; cvt.u32.u64 %0, t; }" : "=r"(a) : "l"(p));
    return a;
}
__device__ __forceinline__ void cp16(uint32_t dst, const void* src) {
    asm volatile("cp.async.cg.shared.global [%0], [%1], 16;" :: "r"(dst), "l"(src));
}
#define CP_COMMIT() asm volatile("cp.async.commit_group;" ::: "memory")
#define CP_WAIT(n)  asm volatile("cp.async.wait_group %0;" :: "n"(n) : "memory")

// ---------------------------------------------------------------------------
// Kernel A0: per-batch compaction map via block scan + zero pad rows
// grid = 64, block = 256 (int4 labels, 4 per thread)   [R7-proven]
// ---------------------------------------------------------------------------
__global__ void __launch_bounds__(256)
scan_kernel(const int* __restrict__ labels)
{
    const int b = blockIdx.x;
    const int tid = threadIdx.x;
    const int warp = tid >> 5, lane = tid & 31;

    __shared__ int s_wtot[8];

    int4 l4 = reinterpret_cast<const int4*>(labels + b * NN)[tid];
    int p0 = (l4.x == 1), p1 = (l4.y == 1), p2 = (l4.z == 1), p3 = (l4.w == 1);
    int tsum = p0 + p1 + p2 + p3;

    int incl = tsum;
#pragma unroll
    for (int o = 1; o < 32; o <<= 1) {
        int v = __shfl_up_sync(0xFFFFFFFFu, incl, o);
        if (lane >= o) incl += v;
    }
    if (lane == 31) s_wtot[warp] = incl;
    __syncthreads();
    if (tid < 8) {
        int v = s_wtot[tid];
#pragma unroll
        for (int o = 1; o < 8; o <<= 1) {
            int u = __shfl_up_sync(0x000000FFu, v, o);
            if (lane >= o) v += u;
        }
        s_wtot[tid] = v;
    }
    __syncthreads();

    int run = (warp > 0 ? s_wtot[warp - 1] : 0) + incl - tsum;
    int base4 = tid * 4;
    int pp[4] = {p0, p1, p2, p3};
#pragma unroll
    for (int j = 0; j < 4; j++) {
        int idx = base4 + j;
        int rank = pp[j] ? run : (idx - run);
        g_dest[b * NN + idx] = (unsigned short)(rank | (pp[j] << 15));
        run += pp[j];
    }

    const int npos = s_wtot[7];
    const int nneg = NN - npos;
    if (tid == 0) {
        g_npos[b] = npos; g_nneg[b] = nneg; g_bsum[b] = 0.0f;
        if (b == 0) g_done = 0u;
    }

    const uint4 z4 = make_uint4(0u, 0u, 0u, 0u);
    int pad_pos = min(NN, ((npos + TM - 1) / TM) * TM);
    int pad_neg = min(NN, ((nneg + TN - 1) / TN) * TN);
    int nzp = (pad_pos - npos) * 16;
    for (int i = tid; i < nzp; i += 256) {
        int r = npos + (i >> 4), c = i & 15;
        reinterpret_cast<uint4*>(g_P + ((size_t)b * NN + r) * ND)[c] = z4;
    }
    int nzn = (pad_neg - nneg) * 16;
    for (int i = tid; i < nzn; i += 256) {
        int r = nneg + (i >> 4), c = i & 15;
        reinterpret_cast<uint4*>(g_Q + ((size_t)b * NN + r) * ND)[c] = z4;
    }
}

// ---------------------------------------------------------------------------
// Kernel A1: normalize + scatter. 4 rows per warp (float4 loads, MLP=4),
// batched shfl reduction, packed bf16x4 stores. grid = (32, 64), 256 thr.
// ---------------------------------------------------------------------------
__global__ void __launch_bounds__(256)
normalize_scatter_kernel(const float* __restrict__ emb)
{
    const int b = blockIdx.y;
    const int wid  = threadIdx.x >> 5;
    const int lane = threadIdx.x & 31;
    const int r0 = blockIdx.x * 32 + wid * 4;     // 4 consecutive rows per warp

    float4 v[4];
    float ss[4];
#pragma unroll
    for (int j = 0; j < 4; j++) {
        v[j] = reinterpret_cast<const float4*>(emb + ((size_t)b * NN + r0 + j) * ND)[lane];
        ss[j] = v[j].x * v[j].x + v[j].y * v[j].y + v[j].z * v[j].z + v[j].w * v[j].w;
    }
#pragma unroll
    for (int o = 16; o > 0; o >>= 1) {
#pragma unroll
        for (int j = 0; j < 4; j++) ss[j] += __shfl_xor_sync(0xFFFFFFFFu, ss[j], o);
    }

#pragma unroll
    for (int j = 0; j < 4; j++) {
        float inv = 1.0f / fmaxf(sqrtf(ss[j]), 1e-12f);
        unsigned short d = g_dest[b * NN + r0 + j];
        int rank  = d & 0x7FFF;
        int ispos = d >> 15;
        __nv_bfloat16* dst = (ispos ? g_P : g_Q) + ((size_t)b * NN + rank) * ND;
        __nv_bfloat162 h0 = __floats2bfloat162_rn(v[j].x * inv, v[j].y * inv);
        __nv_bfloat162 h1 = __floats2bfloat162_rn(v[j].z * inv, v[j].w * inv);
        uint2 pk = make_uint2(*reinterpret_cast<uint32_t*>(&h0),
                              *reinterpret_cast<uint32_t*>(&h1));
        reinterpret_cast<uint2*>(dst)[lane] = pk;
    }
}

// ---------------------------------------------------------------------------
// Kernel B: A-resident streaming GEMM (R7 winner; epilogue gets 4 partials).
// CTA = (ti, b); A loaded once, B tiles double-buffered. grid (8,64), occ 2.
// ---------------------------------------------------------------------------
__global__ void __launch_bounds__(256, 2)
hinge_gemm_kernel(float* __restrict__ out)
{
    extern __shared__ __align__(16) char smem[];
    const uint32_t smem_base = smem_u32(smem);
    const int tid  = threadIdx.x;
    const int warp = tid >> 5;
    const int lane = tid & 31;

    const int ti = blockIdx.x;
    const int b  = blockIdx.y;
    const int npos = g_npos[b];
    const int nneg = g_nneg[b];
    const int njt  = (nneg + TN - 1) / TN;
    const bool active = (ti * TM < npos) && (njt > 0);

    if (active) {
        const char* P  = (const char*)(g_P + ((size_t)b * NN + ti * TM) * ND);
        const char* Qb = (const char*)(g_Q + (size_t)b * NN * ND);
        const uint32_t sAa  = smem_base;
        const uint32_t sB0a = smem_base + TILE_BYTES;

        for (int t = tid; t < TM * 16; t += 256) {
            int r = t >> 4, c = t & 15;
            cp16(sAa + r * ROWB + c * 16, P + (size_t)r * ND * 2 + c * 16);
            cp16(sB0a + r * ROWB + c * 16, Qb + (size_t)r * ND * 2 + c * 16);
        }
        CP_COMMIT();

        const __nv_bfloat16* sA = (const __nv_bfloat16*)(smem);
        const int wrow = warp >> 1;
        const int wcol = warp & 1;

        float s0 = 0.0f, s1 = 0.0f, s2 = 0.0f, s3 = 0.0f;

        for (int tj = 0; tj < njt; tj++) {
            const int cbuf = tj & 1;
            if (tj + 1 < njt) {
                const char* Qn = Qb + (size_t)(tj + 1) * TN * ND * 2;
                uint32_t sBn = smem_base + TILE_BYTES * (1 + ((tj + 1) & 1));
                for (int t = tid; t < TN * 16; t += 256) {
                    int r = t >> 4, c = t & 15;
                    cp16(sBn + r * ROWB + c * 16, Qn + (size_t)r * ND * 2 + c * 16);
                }
                CP_COMMIT();
                CP_WAIT(1);
            } else {
                CP_WAIT(0);
            }
            __syncthreads();

            const __nv_bfloat16* sB =
                (const __nv_bfloat16*)(smem + TILE_BYTES * (1 + cbuf));

            wmma::fragment<wmma::accumulator, 16, 16, 16, float> acc[2][4];
#pragma unroll
            for (int i = 0; i < 2; i++)
#pragma unroll
                for (int j = 0; j < 4; j++) wmma::fill_fragment(acc[i][j], 0.0f);

#pragma unroll
            for (int k = 0; k < ND; k += 16) {
                wmma::fragment<wmma::matrix_a, 16, 16, 16, __nv_bfloat16, wmma::row_major> a[2];
                wmma::fragment<wmma::matrix_b, 16, 16, 16, __nv_bfloat16, wmma::col_major> bb[4];
#pragma unroll
                for (int i = 0; i < 2; i++)
                    wmma::load_matrix_sync(a[i], sA + (wrow * 32 + i * 16) * LDSE + k, LDSE);
#pragma unroll
                for (int j = 0; j < 4; j++)
                    wmma::load_matrix_sync(bb[j], sB + (wcol * 64 + j * 16) * LDSE + k, LDSE);
#pragma unroll
                for (int i = 0; i < 2; i++)
#pragma unroll
                    for (int j = 0; j < 4; j++)
                        wmma::mma_sync(acc[i][j], a[i], bb[j], acc[i][j]);
            }

            // epilogue: 4 independent partial sums (break the FADD RAW chain)
#pragma unroll
            for (int i = 0; i < 2; i++)
#pragma unroll
                for (int j = 0; j < 4; j++) {
#pragma unroll
                    for (int e = 0; e < 8; e += 4) {
                        s0 += fmaxf(acc[i][j].x[e + 0] - THRESH, 0.0f);
                        s1 += fmaxf(acc[i][j].x[e + 1] - THRESH, 0.0f);
                        s2 += fmaxf(acc[i][j].x[e + 2] - THRESH, 0.0f);
                        s3 += fmaxf(acc[i][j].x[e + 3] - THRESH, 0.0f);
                    }
                }

            __syncthreads();
        }

        float s = (s0 + s1) + (s2 + s3);
#pragma unroll
        for (int o = 16; o > 0; o >>= 1) s += __shfl_xor_sync(0xFFFFFFFFu, s, o);
        __shared__ float s_w[8];
        if (lane == 0) s_w[warp] = s;
        __syncthreads();
        if (tid == 0) {
            float ts = 0.0f;
#pragma unroll
            for (int i = 0; i < 8; i++) ts += s_w[i];
            atomicAdd(&g_bsum[b], ts);
        }
    }

    // completion ticket; last CTA computes the final scalar
    __shared__ unsigned int s_rank;
    if (tid == 0) {
        __threadfence();
        s_rank = atomicAdd(&g_done, 1u);
    }
    __syncthreads();
    if (s_rank == GEMM_CTAS - 1 && tid == 0) {
        __threadfence();
        float L = 0.0f, C = 0.0f;
        for (int i = 0; i < NB; i++) {
            int np = g_npos[i], nn = g_nneg[i];
            if (np > 0 && nn > 0) {
                L += g_bsum[i] / (float)nn;
                C += (float)np;
            }
        }
        out[0] = L / fmaxf(C, 1.0f);
    }
}

// ---------------------------------------------------------------------------
extern "C" void kernel_launch(void* const* d_in, const int* in_sizes, int n_in,
                              void* d_out, int out_size)
{
    const float* emb    = (const float*)d_in[0];
    const int*   labels = (const int*)d_in[1];
    float*       out    = (float*)d_out;

    cudaFuncSetAttribute(hinge_gemm_kernel,
                         cudaFuncAttributeMaxDynamicSharedMemorySize, SMEM_DYN);

    scan_kernel<<<NB, 256>>>(labels);

    dim3 gridA(NN / 32, NB);   // (32, 64): 4 rows per warp
    normalize_scatter_kernel<<<gridA, 256>>>(emb);

    dim3 gridB(8, NB);         // (ti, b) = 512 CTAs
    hinge_gemm_kernel<<<gridB, 256, SMEM_DYN>>>(out);
}